// round 2
// baseline (speedup 1.0000x reference)
#include <cuda_runtime.h>
#include <cuda_bf16.h>
#include <stdint.h>

// ---------------------------------------------------------------------------
// AggregationLayer: out[s,:] = mean over edges e with segment_ids[e]==s of
//                   values[gather_idx[e], :]
//   values:      [N_SRC=1e6, 64] f32
//   gather_idx:  [E=4e6] i64 (or i32 if x64 disabled) -- random
//   segment_ids: [E] i64/i32 -- SORTED ascending
//   out:         [S=250e3, 64] f32  (mean per segment; empty segment -> 0)
//
// Design: sorted segs => compute exact segment offsets (lower_bound table),
// then one warp per segment does gather+sum+mean with plain stores.
// No atomics, no zero pass, no divide pass.
// ---------------------------------------------------------------------------

#define D 64
#define MAX_SEGS (1 << 20)

__device__ int g_is64;
__device__ int g_seg_start[MAX_SEGS + 1];

// --- probe index dtype: int64 little-endian => odd 32-bit words are 0 -------
__global__ void detect_kernel(const unsigned int* gi_words) {
    if (threadIdx.x == 0 && blockIdx.x == 0) {
        g_is64 = (gi_words[1] == 0u) & (gi_words[3] == 0u) &
                 (gi_words[5] == 0u) & (gi_words[7] == 0u);
    }
}

// --- build seg_start[0..S] : lower-bound offsets into the edge array --------
template <typename IdxT>
__device__ __forceinline__ void fill_impl(const IdxT* __restrict__ segs,
                                          long long E, int S) {
    long long e = (long long)blockIdx.x * blockDim.x + threadIdx.x;
    if (e > E) return;
    if (e == E) {
        // tail: segments strictly greater than the last seg id start at E
        int last = (int)segs[E - 1];
        for (int t = last + 1; t <= S; ++t) g_seg_start[t] = (int)E;
        return;
    }
    int s  = (int)segs[e];
    int sp = (e == 0) ? -1 : (int)segs[e - 1];
    // all segments t in (sp, s] have lower_bound == e
    for (int t = sp + 1; t <= s; ++t) g_seg_start[t] = (int)e;
}

__global__ void fill_kernel(const void* __restrict__ segs, long long E, int S) {
    if (g_is64) fill_impl<long long>((const long long*)segs, E, S);
    else        fill_impl<int>((const int*)segs, E, S);
}

// --- aggregation: one warp per segment --------------------------------------
template <typename IdxT>
__device__ __forceinline__ void agg_impl(const float* __restrict__ values,
                                         const IdxT* __restrict__ gidx,
                                         float* __restrict__ out, int S) {
    const int lane = threadIdx.x & 31;
    const int seg  = (int)((blockIdx.x * blockDim.x + threadIdx.x) >> 5);
    if (seg >= S) return;

    const int b  = g_seg_start[seg];
    const int e2 = g_seg_start[seg + 1];
    const int cnt = e2 - b;

    float ax = 0.0f, ay = 0.0f;
    const int col = lane * 2;

    for (int base = b; base < e2; base += 32) {
        const int m = min(32, e2 - base);
        // coalesced cooperative index load
        long long my_idx = (lane < m) ? (long long)gidx[base + lane] : 0;
        #pragma unroll 4
        for (int j = 0; j < m; ++j) {
            const long long idx = __shfl_sync(0xffffffffu, my_idx, j);
            const float2 v = *(const float2*)(values + idx * (long long)D + col);
            ax += v.x; ay += v.y;
        }
    }

    const float inv = (cnt > 0) ? (1.0f / (float)cnt) : 0.0f;
    float2 r; r.x = ax * inv; r.y = ay * inv;
    *(float2*)(out + (long long)seg * D + col) = r;
}

__global__ void agg_kernel(const float* __restrict__ values,
                           const void* __restrict__ gidx,
                           float* __restrict__ out, int S) {
    if (g_is64)
        agg_impl<long long>(values, (const long long*)gidx, out, S);
    else
        agg_impl<int>(values, (const int*)gidx, out, S);
}

// ---------------------------------------------------------------------------
extern "C" void kernel_launch(void* const* d_in, const int* in_sizes, int n_in,
                              void* d_out, int out_size) {
    const float* values = (const float*)d_in[0];
    const void*  gidx   = d_in[1];
    const void*  segs   = d_in[2];
    float*       out    = (float*)d_out;

    const long long E = (long long)in_sizes[1];   // gather_idx element count
    const int       S = (int)((long long)out_size / D);

    // 1) index-width probe (sets g_is64 used by both subsequent kernels)
    detect_kernel<<<1, 32>>>((const unsigned int*)gidx);

    // 2) segment offset table from sorted segment_ids
    {
        const int threads = 256;
        const long long blocks = (E + 1 + threads - 1) / threads;
        fill_kernel<<<(unsigned)blocks, threads>>>(segs, E, S);
    }

    // 3) gather + segmented mean, one warp per segment, plain stores
    {
        const int threads = 256;                      // 8 warps / block
        const int blocks  = (S + 7) / 8;
        agg_kernel<<<blocks, threads>>>(values, gidx, out, S);
    }
}